// round 3
// baseline (speedup 1.0000x reference)
#include <cuda_runtime.h>
#include <cuda_bf16.h>
#include <math.h>

// Problem constants: C=1024 classes, S=16 utterances, D=512 dims.
#define CC   1024
#define SS   16
#define DD   512
#define RR_T (CC*SS)        // 16384 rows
#define EPSV 1e-8f

// Scratch (no cudaMalloc allowed)
__device__ __align__(128) float g_meanT[DD * CC];   // meanT[d][k] = mean_c[k][d]  (2 MB)
__device__ __align__(128) float g_nmean[CC];
__device__ __align__(128) float g_nx[RR_T];
__device__ double g_acc;

// ---------------------------------------------------------------------------
// Kernel A: per-class mean (transposed), nmean, per-row nx. 1024 blocks x 512 thr.
// ---------------------------------------------------------------------------
__device__ __forceinline__ float blockReduceSum512(float v, float* red) {
    #pragma unroll
    for (int o = 16; o; o >>= 1) v += __shfl_xor_sync(0xffffffffu, v, o);
    int wid = threadIdx.x >> 5, lane = threadIdx.x & 31;
    if (lane == 0) red[wid] = v;
    __syncthreads();
    float s = 0.f;
    if (wid == 0) {
        s = (lane < 16) ? red[lane] : 0.f;
        #pragma unroll
        for (int o = 8; o; o >>= 1) s += __shfl_xor_sync(0xffffffffu, s, o);
    }
    __syncthreads();
    return s;  // valid on warp 0
}

__global__ void prep_kernel(const float* __restrict__ x) {
    __shared__ float red[16];
    const int j = blockIdx.x;
    const int d = threadIdx.x;
    if (j == 0 && d == 0) g_acc = 0.0;

    float xv[SS];
    float s = 0.f;
    #pragma unroll
    for (int i = 0; i < SS; i++) {
        xv[i] = x[(j * SS + i) * DD + d];
        s += xv[i];
    }
    float mean = s * (1.f / (float)SS);
    g_meanT[d * CC + j] = mean;

    float nm2 = blockReduceSum512(mean * mean, red);
    if (threadIdx.x == 0) g_nmean[j] = sqrtf(nm2);

    #pragma unroll
    for (int i = 0; i < SS; i++) {
        float u = blockReduceSum512(xv[i] * xv[i], red);
        if (threadIdx.x == 0) g_nx[j * SS + i] = sqrtf(u);
    }
}

// ---------------------------------------------------------------------------
// Kernel B: GEMM G = X(16384x512) @ meanT(512x1024) fused with diag-fix + LSE.
// Block: BM=32 rows x full N=1024. 512 threads = (ty 0..3) x (tx 0..127).
// Thread tile: 8 rows x 8 cols, cols n = tx + 128*c (conflict-free LDS).
// ---------------------------------------------------------------------------
#define BM 32
#define BK 8

__global__ __launch_bounds__(512, 1)
void gemm_lse_kernel(const float* __restrict__ x,
                     const float* __restrict__ wptr,
                     const float* __restrict__ bptr) {
    __shared__ __align__(16) float Ms[BK * CC];   // 32 KB
    __shared__ float As[BK * BM];                 // 1 KB
    __shared__ float red[4][8][4];
    __shared__ float diagv[4][8];

    const int tid = threadIdx.x;
    const int ty  = tid >> 7;      // 0..3
    const int tx  = tid & 127;     // 0..127
    const int r0  = blockIdx.x * BM;

    float acc[8][8];
    #pragma unroll
    for (int a = 0; a < 8; a++)
        #pragma unroll
        for (int b2 = 0; b2 < 8; b2++) acc[a][b2] = 0.f;

    // prefetch registers
    float4 pm[4];
    float4 pa;
    const bool hasA  = (tid < 64);
    const int  rrA   = tid >> 1;
    const int  partA = tid & 1;

    #pragma unroll
    for (int q = 0; q < 4; q++) {
        int f4 = tid + 512 * q, kk = f4 >> 8, n4 = f4 & 255;
        pm[q] = *(const float4*)&g_meanT[kk * CC + n4 * 4];
    }
    if (hasA) pa = *(const float4*)&x[(r0 + rrA) * DD + partA * 4];

    for (int kd0 = 0; kd0 < DD; kd0 += BK) {
        // stage current tile to smem
        #pragma unroll
        for (int q = 0; q < 4; q++) {
            int f4 = tid + 512 * q, kk = f4 >> 8, n4 = f4 & 255;
            *(float4*)&Ms[kk * CC + n4 * 4] = pm[q];
        }
        if (hasA) {
            As[(partA * 4 + 0) * BM + rrA] = pa.x;
            As[(partA * 4 + 1) * BM + rrA] = pa.y;
            As[(partA * 4 + 2) * BM + rrA] = pa.z;
            As[(partA * 4 + 3) * BM + rrA] = pa.w;
        }
        __syncthreads();

        // prefetch next tile (hidden under the FMA block below)
        int kn = kd0 + BK;
        if (kn < DD) {
            #pragma unroll
            for (int q = 0; q < 4; q++) {
                int f4 = tid + 512 * q, kk = f4 >> 8, n4 = f4 & 255;
                pm[q] = *(const float4*)&g_meanT[(kn + kk) * CC + n4 * 4];
            }
            if (hasA) pa = *(const float4*)&x[(r0 + rrA) * DD + kn + partA * 4];
        }

        #pragma unroll
        for (int kk = 0; kk < BK; kk++) {
            float a[8], m[8];
            #pragma unroll
            for (int rr = 0; rr < 8; rr++) a[rr] = As[kk * BM + ty * 8 + rr];
            #pragma unroll
            for (int c = 0; c < 8; c++) m[c] = Ms[kk * CC + tx + 128 * c];
            #pragma unroll
            for (int rr = 0; rr < 8; rr++)
                #pragma unroll
                for (int c = 0; c < 8; c++)
                    acc[rr][c] = fmaf(a[rr], m[c], acc[rr][c]);
        }
        __syncthreads();
    }

    // ---------------- fused epilogue: diag fix + LSE + loss ----------------
    const float wv = wptr[0];
    const float bv = bptr[0];
    // stable softplus (matches jax.nn.softplus in fp32)
    const float wp = fmaxf(wv, 0.f) + log1pf(expf(-fabsf(wv)));

    float nmv[8];
    #pragma unroll
    for (int c = 0; c < 8; c++) nmv[c] = g_nmean[tx + 128 * c];

    const int lane = tid & 31;
    const int w4   = tx >> 5;
    float rmax[8];

    #pragma unroll
    for (int rr = 0; rr < 8; rr++) {
        const int r  = r0 + ty * 8 + rr;
        const int j  = r >> 4;                 // class of this row
        const float nxr = g_nx[r];
        const float nx2 = nxr * nxr;
        float lmax = -1e30f;
        #pragma unroll
        for (int c = 0; c < 8; c++) {
            const int n = tx + 128 * c;
            const float G = acc[rr][c];
            float sim;
            if (n == j) {
                // leave-one-out positive, derived from the same dot product:
                // x.loo = (16G - |x|^2)/15 ; |loo|^2 = (256 nm^2 - 32G + |x|^2)/225
                float dotpos = (16.f * G - nx2) * (1.f / 15.f);
                float t2 = fmaxf(256.f * nmv[c] * nmv[c] - 32.f * G + nx2, 0.f);
                float nloo = sqrtf(t2) * (1.f / 15.f);
                sim = dotpos / fmaxf(nxr * nloo, EPSV);
            } else {
                sim = G / fmaxf(nxr * nmv[c], EPSV);
            }
            float l = fmaf(wp, sim, bv);
            acc[rr][c] = l;                    // reuse accumulators as logits
            if (n == j) diagv[ty][rr] = l;
            lmax = fmaxf(lmax, l);
        }
        #pragma unroll
        for (int o = 16; o; o >>= 1)
            lmax = fmaxf(lmax, __shfl_xor_sync(0xffffffffu, lmax, o));
        if (lane == 0) red[ty][rr][w4] = lmax;
    }
    __syncthreads();
    #pragma unroll
    for (int rr = 0; rr < 8; rr++)
        rmax[rr] = fmaxf(fmaxf(red[ty][rr][0], red[ty][rr][1]),
                         fmaxf(red[ty][rr][2], red[ty][rr][3]));
    __syncthreads();

    #pragma unroll
    for (int rr = 0; rr < 8; rr++) {
        float s = 0.f;
        #pragma unroll
        for (int c = 0; c < 8; c++) s += __expf(acc[rr][c] - rmax[rr]);
        #pragma unroll
        for (int o = 16; o; o >>= 1) s += __shfl_xor_sync(0xffffffffu, s, o);
        if (lane == 0) red[ty][rr][w4] = s;
    }
    __syncthreads();

    if (tx == 0) {
        float ll = 0.f;
        #pragma unroll
        for (int rr = 0; rr < 8; rr++) {
            float s = red[ty][rr][0] + red[ty][rr][1] + red[ty][rr][2] + red[ty][rr][3];
            ll += rmax[rr] + logf(s) - diagv[ty][rr];
        }
        atomicAdd(&g_acc, (double)ll);
    }
}

// ---------------------------------------------------------------------------
__global__ void finish_kernel(float* __restrict__ out) {
    out[0] = (float)(g_acc * (1.0 / (double)RR_T));
}

extern "C" void kernel_launch(void* const* d_in, const int* in_sizes, int n_in,
                              void* d_out, int out_size) {
    (void)in_sizes; (void)n_in; (void)out_size;
    const float* x = (const float*)d_in[0];
    const float* w = (const float*)d_in[1];
    const float* b = (const float*)d_in[2];
    float* out = (float*)d_out;

    prep_kernel<<<CC, DD>>>(x);
    gemm_lse_kernel<<<RR_T / BM, 512>>>(x, w, b);
    finish_kernel<<<1, 1>>>(out);
}

// round 9
// speedup vs baseline: 7.9582x; 7.9582x over previous
#include <cuda_runtime.h>
#include <cuda_bf16.h>
#include <math.h>
#include <stdint.h>

// Problem constants
#define CC   1024
#define SS   16
#define DD   512
#define RR_T (CC*SS)        // 16384 rows

// GEMM tiling: block 128(M) x 128(N), K-chunk 64 bf16, 256 threads (8 warps)
#define MT 128
#define NTB 128
#define KC 64
#define NCHUNK (DD/KC)      // 8
#define NBLK (CC/NTB)       // 8

// Dynamic smem: 2 stages x (A 16K + B 16K) + epilogue
#define STG      32768
#define OFF_B    16384
#define OFF_INM  65536      // 128 floats
#define OFF_PS   66048      // 128*2 floats
#define DSMEM    67072

// Device scratch (no cudaMalloc allowed)
__device__ __align__(1024) __nv_bfloat16 g_xhi[RR_T*DD];   // 16.8 MB
__device__ __align__(1024) __nv_bfloat16 g_mhi[CC*DD];     // 1 MB
__device__ __align__(128) float g_nx[RR_T];
__device__ __align__(128) float g_invnx[RR_T];
__device__ __align__(128) float g_nm[CC];
__device__ __align__(128) float g_invnm[CC];
__device__ __align__(128) float g_dotm[RR_T];              // exact fp32 diag dot
__device__ __align__(128) float g_psum[RR_T*NBLK];         // 512 KB
__device__ double g_acc;

// ---------------------------------------------------------------------------
__device__ __forceinline__ uint32_t smem_u32(const void* p) {
    uint32_t a;
    asm("{ .reg .u64 t; cvta.to.shared.u64 t, %1; cvt.u32.u64 %0, t; }"
        : "=r"(a) : "l"(p));
    return a;
}
#define SWZ(o) ((o) ^ (((o) >> 3) & 0x70))

__device__ __forceinline__ void cpa16(uint32_t dst, const void* src) {
    asm volatile("cp.async.cg.shared.global [%0], [%1], 16;"
                 :: "r"(dst), "l"(src) : "memory");
}
__device__ __forceinline__ void ldsm_x4(uint32_t* r, uint32_t addr) {
    asm volatile("ldmatrix.sync.aligned.m8n8.x4.shared.b16 {%0,%1,%2,%3}, [%4];"
                 : "=r"(r[0]), "=r"(r[1]), "=r"(r[2]), "=r"(r[3]) : "r"(addr));
}
__device__ __forceinline__ void ldsm_x4t(uint32_t* r, uint32_t addr) {
    asm volatile("ldmatrix.sync.aligned.m8n8.x4.trans.shared.b16 {%0,%1,%2,%3}, [%4];"
                 : "=r"(r[0]), "=r"(r[1]), "=r"(r[2]), "=r"(r[3]) : "r"(addr));
}
__device__ __forceinline__ void mma16816(float* d, const uint32_t* a, const uint32_t* b) {
    asm volatile(
        "mma.sync.aligned.m16n8k16.row.col.f32.bf16.bf16.f32 "
        "{%0,%1,%2,%3}, {%4,%5,%6,%7}, {%8,%9}, {%0,%1,%2,%3};"
        : "+f"(d[0]), "+f"(d[1]), "+f"(d[2]), "+f"(d[3])
        : "r"(a[0]), "r"(a[1]), "r"(a[2]), "r"(a[3]), "r"(b[0]), "r"(b[1]));
}

// FMA-pipe exp for args in [-2wp, 0]
__device__ __forceinline__ float fexp(float u) {
    float t = u * 1.4426950408889634f;
    int   ki = __float2int_rn(t);
    float f = t - (float)ki;
    float p = 1.3333558e-3f;
    p = fmaf(p, f, 9.6181291e-3f);
    p = fmaf(p, f, 5.5504109e-2f);
    p = fmaf(p, f, 2.4022651e-1f);
    p = fmaf(p, f, 6.9314718e-1f);
    p = fmaf(p, f, 1.0f);
    return p * __int_as_float((ki + 127) << 23);
}

__device__ __forceinline__ float blockReduceSum512(float v, float* red) {
    #pragma unroll
    for (int o = 16; o; o >>= 1) v += __shfl_xor_sync(0xffffffffu, v, o);
    int wid = threadIdx.x >> 5, lane = threadIdx.x & 31;
    if (lane == 0) red[wid] = v;
    __syncthreads();
    float s = 0.f;
    if (wid == 0) {
        s = (lane < 16) ? red[lane] : 0.f;
        #pragma unroll
        for (int o = 8; o; o >>= 1) s += __shfl_xor_sync(0xffffffffu, s, o);
    }
    __syncthreads();
    return s;
}

// ---------------------------------------------------------------------------
// Kernel A: bf16 casts, means, norms, exact fp32 diagonal dots.
// 1024 blocks x 512 threads (one block per class, thread = dim d).
// ---------------------------------------------------------------------------
__global__ __launch_bounds__(512)
void prep_kernel(const float* __restrict__ x) {
    __shared__ float sq[SS * DD];   // 32 KB
    __shared__ float red[16];
    const int j = blockIdx.x;
    const int d = threadIdx.x;
    if (j == 0 && d == 0) g_acc = 0.0;

    float xv[SS], ssum = 0.f;
    #pragma unroll
    for (int i = 0; i < SS; i++) {
        xv[i] = x[(size_t)(j * SS + i) * DD + d];
        ssum += xv[i];
    }
    float mean = ssum * (1.f / (float)SS);
    g_mhi[(size_t)j * DD + d] = __float2bfloat16(mean);

    #pragma unroll
    for (int i = 0; i < SS; i++) {
        g_xhi[(size_t)(j * SS + i) * DD + d] = __float2bfloat16(xv[i]);
        sq[i * DD + d] = xv[i] * xv[i];
    }

    float nm2 = blockReduceSum512(mean * mean, red);  // syncs; orders sq writes
    if (d == 0) {
        float nm = sqrtf(nm2);
        g_nm[j] = nm;
        g_invnm[j] = 1.f / nm;
    }

    const int w = d >> 5, lane = d & 31;
    float s = 0.f;
    #pragma unroll
    for (int t = 0; t < 16; t++) s += sq[w * DD + lane + 32 * t];
    #pragma unroll
    for (int o = 16; o; o >>= 1) s += __shfl_xor_sync(0xffffffffu, s, o);
    if (lane == 0) {
        float nx = sqrtf(s);
        g_nx[j * SS + w] = nx;
        g_invnx[j * SS + w] = 1.f / nx;
    }

    __syncthreads();
    #pragma unroll
    for (int i = 0; i < SS; i++) sq[i * DD + d] = xv[i] * mean;
    __syncthreads();
    float s2 = 0.f;
    #pragma unroll
    for (int t = 0; t < 16; t++) s2 += sq[w * DD + lane + 32 * t];
    #pragma unroll
    for (int o = 16; o; o >>= 1) s2 += __shfl_xor_sync(0xffffffffu, s2, o);
    if (lane == 0) g_dotm[j * SS + w] = s2;
}

// ---------------------------------------------------------------------------
// Kernel B: bf16 HMMA GEMM (mma.sync) + fused off-diagonal exp-sum epilogue
// ---------------------------------------------------------------------------
__device__ __forceinline__ void stage_load(uint32_t base, int c, int r0, int n0, int tid) {
    const int koff = c * KC;
    #pragma unroll
    for (int q = 0; q < 4; q++) {
        int qa = tid + 256 * q;
        int row = qa >> 3, qq = qa & 7;
        uint32_t sw = SWZ(row * 128 + qq * 16);
        cpa16(base + sw,           g_xhi + (size_t)(r0 + row) * DD + koff + qq * 8);
        cpa16(base + OFF_B + sw,   g_mhi + (size_t)(n0 + row) * DD + koff + qq * 8);
    }
}

__global__ __launch_bounds__(256, 2)
void gemm_lse_kernel(const float* __restrict__ wptr) {
    extern __shared__ __align__(1024) char sm[];
    const uint32_t sb = smem_u32(sm);
    const int tid  = threadIdx.x;
    const int lane = tid & 31;
    const int wid  = tid >> 5;
    const int warpM = wid & 3;         // 0..3  (32-row tiles)
    const int warpN = wid >> 2;        // 0..1  (64-col tiles)
    const int r0 = blockIdx.x * MT;
    const int n0 = blockIdx.y * NTB;

    float* s_invnm = (float*)(sm + OFF_INM);
    float* s_ps    = (float*)(sm + OFF_PS);
    if (tid < NTB) s_invnm[tid] = g_invnm[n0 + tid];

    float acc[2][8][4];
    #pragma unroll
    for (int mf = 0; mf < 2; mf++)
        #pragma unroll
        for (int nf = 0; nf < 8; nf++)
            #pragma unroll
            for (int q = 0; q < 4; q++) acc[mf][nf][q] = 0.f;

    const int g  = lane >> 3;          // ldmatrix address group
    const int ri = lane & 7;
    const int mrow = warpM * 32;
    const int arow0 = mrow + (g & 1) * 8 + ri;           // + mf*16
    const int acol0 = (g >> 1) * 16;                     // + kk*32
    const int brow0 = warpN * 64 + (g >> 1) * 8 + ri;    // + nf2*16
    const int bcol0 = (g & 1) * 16;                      // + kk*32

    stage_load(sb, 0, r0, n0, tid);
    asm volatile("cp.async.commit_group;" ::: "memory");

    for (int c = 0; c < NCHUNK; ++c) {
        if (c + 1 < NCHUNK) {
            stage_load(sb + ((c + 1) & 1) * STG, c + 1, r0, n0, tid);
            asm volatile("cp.async.commit_group;" ::: "memory");
            asm volatile("cp.async.wait_group 1;" ::: "memory");
        } else {
            asm volatile("cp.async.wait_group 0;" ::: "memory");
        }
        __syncthreads();

        const uint32_t aB = sb + (c & 1) * STG;
        const uint32_t bB = aB + OFF_B;
        #pragma unroll
        for (int kk = 0; kk < 4; kk++) {
            uint32_t a[2][4], b[8][2];
            #pragma unroll
            for (int mf = 0; mf < 2; mf++)
                ldsm_x4(a[mf], aB + SWZ((arow0 + mf * 16) * 128 + kk * 32 + acol0));
            #pragma unroll
            for (int nf2 = 0; nf2 < 4; nf2++) {
                uint32_t t[4];
                ldsm_x4t(t, bB + SWZ((brow0 + nf2 * 16) * 128 + kk * 32 + bcol0));
                b[nf2 * 2][0]     = t[0]; b[nf2 * 2][1]     = t[1];
                b[nf2 * 2 + 1][0] = t[2]; b[nf2 * 2 + 1][1] = t[3];
            }
            #pragma unroll
            for (int mf = 0; mf < 2; mf++)
                #pragma unroll
                for (int nf = 0; nf < 8; nf++)
                    mma16816(acc[mf][nf], a[mf], b[nf]);
        }
        __syncthreads();
    }

    // -------- epilogue: off-diagonal exp-sum per row --------
    const float wv = wptr[0];
    const float wp = fmaxf(wv, 0.f) + log1pf(expf(-fabsf(wv)));

    float invr[2][2];
    int jcl[2][2];
    #pragma unroll
    for (int mf = 0; mf < 2; mf++)
        #pragma unroll
        for (int fr = 0; fr < 2; fr++) {
            int r = r0 + mrow + mf * 16 + fr * 8 + (lane >> 2);
            invr[mf][fr] = g_invnx[r];
            jcl[mf][fr]  = r >> 4;
        }

    float rsum[2][2] = {{0.f, 0.f}, {0.f, 0.f}};
    #pragma unroll
    for (int mf = 0; mf < 2; mf++)
        #pragma unroll
        for (int nf = 0; nf < 8; nf++) {
            const int nl0 = warpN * 64 + nf * 8 + (lane & 3) * 2;
            const float im0 = s_invnm[nl0], im1 = s_invnm[nl0 + 1];
            #pragma unroll
            for (int fr = 0; fr < 2; fr++) {
                const float a0 = acc[mf][nf][fr * 2 + 0];
                const float a1 = acc[mf][nf][fr * 2 + 1];
                const float iv = invr[mf][fr];
                const int jc = jcl[mf][fr];
                if (n0 + nl0 != jc)
                    rsum[mf][fr] += fexp(fmaf(wp, a0 * iv * im0, -wp));
                if (n0 + nl0 + 1 != jc)
                    rsum[mf][fr] += fexp(fmaf(wp, a1 * iv * im1, -wp));
            }
        }

    // reduce over the 4 lanes of each quad (same rows, different cols)
    #pragma unroll
    for (int mf = 0; mf < 2; mf++)
        #pragma unroll
        for (int fr = 0; fr < 2; fr++) {
            float v = rsum[mf][fr];
            v += __shfl_xor_sync(0xffffffffu, v, 1);
            v += __shfl_xor_sync(0xffffffffu, v, 2);
            if ((lane & 3) == 0)
                s_ps[(mrow + mf * 16 + fr * 8 + (lane >> 2)) * 2 + warpN] = v;
        }
    __syncthreads();

    if (tid < MT)
        g_psum[(size_t)(r0 + tid) * NBLK + blockIdx.y] =
            s_ps[tid * 2 + 0] + s_ps[tid * 2 + 1];
}

// ---------------------------------------------------------------------------
// Kernel C: add exact diagonal term, finish per-row loss, reduce
// ---------------------------------------------------------------------------
__global__ __launch_bounds__(512)
void combine_kernel(const float* __restrict__ wptr) {
    __shared__ float red[16];
    const int r = blockIdx.x * 512 + threadIdx.x;
    const float wv = wptr[0];
    const float wp = fmaxf(wv, 0.f) + log1pf(expf(-fabsf(wv)));

    float tot = 0.f;
    #pragma unroll
    for (int t = 0; t < NBLK; t++) tot += g_psum[(size_t)r * NBLK + t];

    const float nx = g_nx[r];
    const float nx2 = nx * nx;
    const float nm = g_nm[r >> 4];
    const float dm = g_dotm[r];
    float dotpos = fmaf(16.f, dm, -nx2) * (1.f / 15.f);
    float t2 = fmaxf(fmaf(256.f, nm * nm, fmaf(-32.f, dm, nx2)), 0.f);
    float nloo = sqrtf(t2) * (1.f / 15.f);
    float simp = dotpos / fmaxf(nx * nloo, 1e-8f);
    tot += fexp(fmaf(wp, simp, -wp));

    float loss = fmaf(-wp, simp, wp) + logf(tot);
    float s = blockReduceSum512(loss, red);
    if (threadIdx.x == 0) atomicAdd(&g_acc, (double)s);
}

__global__ void finish_kernel(float* __restrict__ out) {
    out[0] = (float)(g_acc * (1.0 / (double)RR_T));
}

// ---------------------------------------------------------------------------
extern "C" void kernel_launch(void* const* d_in, const int* in_sizes, int n_in,
                              void* d_out, int out_size) {
    (void)in_sizes; (void)n_in; (void)out_size;
    const float* x = (const float*)d_in[0];
    const float* w = (const float*)d_in[1];
    float* out = (float*)d_out;

    cudaFuncSetAttribute(gemm_lse_kernel,
                         cudaFuncAttributeMaxDynamicSharedMemorySize, DSMEM);

    prep_kernel<<<CC, 512>>>(x);
    dim3 grid(RR_T / MT, CC / NTB);   // 128 x 8
    gemm_lse_kernel<<<grid, 256, DSMEM>>>(w);
    combine_kernel<<<RR_T / 512, 512>>>(w);
    finish_kernel<<<1, 1>>>(out);
}